// round 1
// baseline (speedup 1.0000x reference)
#include <cuda_runtime.h>
#include <cuda_bf16.h>
#include <math.h>

// Problem constants (match reference; guarded dynamically too)
#define MAXN 100000
#define MAXE 1600000
#define DIM  256

// Scratch (device globals: allocation-free per harness rules)
__device__ float g_H[(size_t)MAXN * DIM];     // right_embed @ W1
__device__ float g_AGG[(size_t)MAXN * DIM];   // relu(segment_sum(...))
__device__ int   g_rowptr[MAXN + 1];

// ---------------------------------------------------------------------------
// Kernel 1: row_ptr via binary search over sorted edge_rows
// ---------------------------------------------------------------------------
__global__ void build_rowptr(const int* __restrict__ rows, int E, int Nn) {
    int r = blockIdx.x * blockDim.x + threadIdx.x;
    if (r > Nn) return;
    int lo = 0, hi = E;
    while (lo < hi) {
        int mid = (lo + hi) >> 1;
        if (rows[mid] < r) lo = mid + 1; else hi = mid;
    }
    g_rowptr[r] = lo;
}

// ---------------------------------------------------------------------------
// Kernel 2: H = X @ W1  (classic 128x128x8 SGEMM, fp32)
// ---------------------------------------------------------------------------
#define BM 128
#define BN 128
#define BK 8

__global__ __launch_bounds__(256, 2)
void gemm_h(const float* __restrict__ A, const float* __restrict__ B, int M) {
    __shared__ float As[BK][BM];
    __shared__ float Bs[BK][BN];

    const int bx = blockIdx.x;           // n-block (0..1)
    const int by = blockIdx.y;           // m-block
    const int tid = threadIdx.x;
    const int tx = tid & 15;             // 0..15
    const int ty = tid >> 4;             // 0..15
    const int row0 = by * BM;

    // A tile loader: thread -> (a_row, a_k4)
    const int a_row = tid >> 1;          // 0..127
    const int a_k   = (tid & 1) * 4;     // 0 or 4
    // B tile loader
    const int b_k = tid >> 5;            // 0..7
    const int b_n = (tid & 31) * 4;      // 0..124

    const bool a_valid = (row0 + a_row) < M;
    const float* Aptr = A + (size_t)(a_valid ? (row0 + a_row) : 0) * DIM + a_k;
    const float* Bptr = B + (size_t)b_k * DIM + bx * BN + b_n;

    float acc[8][8];
#pragma unroll
    for (int i = 0; i < 8; i++)
#pragma unroll
        for (int j = 0; j < 8; j++) acc[i][j] = 0.f;

    for (int k0 = 0; k0 < DIM; k0 += BK) {
        float4 av = a_valid ? *(const float4*)(Aptr + k0) : make_float4(0.f, 0.f, 0.f, 0.f);
        float4 bv = *(const float4*)(Bptr + (size_t)k0 * DIM);
        __syncthreads();
        As[a_k + 0][a_row] = av.x;
        As[a_k + 1][a_row] = av.y;
        As[a_k + 2][a_row] = av.z;
        As[a_k + 3][a_row] = av.w;
        *(float4*)&Bs[b_k][b_n] = bv;
        __syncthreads();
#pragma unroll
        for (int k = 0; k < BK; k++) {
            float4 ra0 = *(float4*)&As[k][ty * 8];
            float4 ra1 = *(float4*)&As[k][ty * 8 + 4];
            float4 rb0 = *(float4*)&Bs[k][tx * 8];
            float4 rb1 = *(float4*)&Bs[k][tx * 8 + 4];
            float ra[8] = {ra0.x, ra0.y, ra0.z, ra0.w, ra1.x, ra1.y, ra1.z, ra1.w};
            float rb[8] = {rb0.x, rb0.y, rb0.z, rb0.w, rb1.x, rb1.y, rb1.z, rb1.w};
#pragma unroll
            for (int i = 0; i < 8; i++)
#pragma unroll
                for (int j = 0; j < 8; j++) acc[i][j] = fmaf(ra[i], rb[j], acc[i][j]);
        }
    }

#pragma unroll
    for (int i = 0; i < 8; i++) {
        int m = row0 + ty * 8 + i;
        if (m >= M) continue;
        float* cptr = g_H + (size_t)m * DIM + bx * BN + tx * 8;
        *(float4*)(cptr + 0) = make_float4(acc[i][0], acc[i][1], acc[i][2], acc[i][3]);
        *(float4*)(cptr + 4) = make_float4(acc[i][4], acc[i][5], acc[i][6], acc[i][7]);
    }
}

// ---------------------------------------------------------------------------
// Kernel 3: SpMM + ReLU. One block per row; rows sorted -> no atomics.
// ---------------------------------------------------------------------------
#define ECHUNK 256

__global__ __launch_bounds__(256)
void spmm_relu(const float* __restrict__ ev, const int* __restrict__ ec) {
    const int r = blockIdx.x;
    const int tid = threadIdx.x;
    const int s = g_rowptr[r];
    const int e = g_rowptr[r + 1];

    __shared__ int   scol[ECHUNK];
    __shared__ float sval[ECHUNK];

    float acc0 = 0.f, acc1 = 0.f, acc2 = 0.f, acc3 = 0.f;

    for (int base = s; base < e; base += ECHUNK) {
        int cnt = min(ECHUNK, e - base);
        if (tid < cnt) {
            scol[tid] = ec[base + tid];
            sval[tid] = ev[base + tid];
        }
        __syncthreads();
        int i = 0;
        for (; i + 4 <= cnt; i += 4) {
            acc0 = fmaf(sval[i + 0], g_H[(size_t)scol[i + 0] * DIM + tid], acc0);
            acc1 = fmaf(sval[i + 1], g_H[(size_t)scol[i + 1] * DIM + tid], acc1);
            acc2 = fmaf(sval[i + 2], g_H[(size_t)scol[i + 2] * DIM + tid], acc2);
            acc3 = fmaf(sval[i + 3], g_H[(size_t)scol[i + 3] * DIM + tid], acc3);
        }
        for (; i < cnt; i++)
            acc0 = fmaf(sval[i], g_H[(size_t)scol[i] * DIM + tid], acc0);
        __syncthreads();
    }
    float acc = (acc0 + acc1) + (acc2 + acc3);
    g_AGG[(size_t)r * DIM + tid] = fmaxf(acc, 0.f);
}

// ---------------------------------------------------------------------------
// Kernel 4: gated GEMM: gate = sigmoid(X[perm] @ Wr + br);
//           out = gate * AGG + (1-gate) * X[perm]
// ---------------------------------------------------------------------------
__global__ __launch_bounds__(256, 2)
void gemm_gate(const float* __restrict__ X, const float* __restrict__ Wr,
               const float* __restrict__ br, const int* __restrict__ perm,
               float* __restrict__ out, int M) {
    __shared__ float As[BK][BM];
    __shared__ float Bs[BK][BN];
    __shared__ int pm_s[BM];

    const int bx = blockIdx.x;
    const int by = blockIdx.y;
    const int tid = threadIdx.x;
    const int tx = tid & 15;
    const int ty = tid >> 4;
    const int row0 = by * BM;

    if (tid < BM) {
        int m = row0 + tid;
        pm_s[tid] = (m < M) ? perm[m] : 0;
    }
    __syncthreads();

    const int a_row = tid >> 1;
    const int a_k   = (tid & 1) * 4;
    const int b_k = tid >> 5;
    const int b_n = (tid & 31) * 4;

    const bool a_valid = (row0 + a_row) < M;
    const float* Aptr = X + (size_t)pm_s[a_row] * DIM + a_k;
    const float* Bptr = Wr + (size_t)b_k * DIM + bx * BN + b_n;

    float acc[8][8];
#pragma unroll
    for (int i = 0; i < 8; i++)
#pragma unroll
        for (int j = 0; j < 8; j++) acc[i][j] = 0.f;

    for (int k0 = 0; k0 < DIM; k0 += BK) {
        float4 av = a_valid ? *(const float4*)(Aptr + k0) : make_float4(0.f, 0.f, 0.f, 0.f);
        float4 bv = *(const float4*)(Bptr + (size_t)k0 * DIM);
        __syncthreads();
        As[a_k + 0][a_row] = av.x;
        As[a_k + 1][a_row] = av.y;
        As[a_k + 2][a_row] = av.z;
        As[a_k + 3][a_row] = av.w;
        *(float4*)&Bs[b_k][b_n] = bv;
        __syncthreads();
#pragma unroll
        for (int k = 0; k < BK; k++) {
            float4 ra0 = *(float4*)&As[k][ty * 8];
            float4 ra1 = *(float4*)&As[k][ty * 8 + 4];
            float4 rb0 = *(float4*)&Bs[k][tx * 8];
            float4 rb1 = *(float4*)&Bs[k][tx * 8 + 4];
            float ra[8] = {ra0.x, ra0.y, ra0.z, ra0.w, ra1.x, ra1.y, ra1.z, ra1.w};
            float rb[8] = {rb0.x, rb0.y, rb0.z, rb0.w, rb1.x, rb1.y, rb1.z, rb1.w};
#pragma unroll
            for (int i = 0; i < 8; i++)
#pragma unroll
                for (int j = 0; j < 8; j++) acc[i][j] = fmaf(ra[i], rb[j], acc[i][j]);
        }
    }

    // bias for this thread's 8 columns
    float brv[8];
#pragma unroll
    for (int j = 0; j < 8; j++) brv[j] = br[bx * BN + tx * 8 + j];

    // epilogue: sigmoid gate + highway blend
#pragma unroll
    for (int i = 0; i < 8; i++) {
        int m = row0 + ty * 8 + i;
        if (m >= M) continue;
        int lrow = pm_s[ty * 8 + i];
        const float* lptr = X + (size_t)lrow * DIM + bx * BN + tx * 8;
        const float* aptr = g_AGG + (size_t)m * DIM + bx * BN + tx * 8;
        float* optr = out + (size_t)m * DIM + bx * BN + tx * 8;
#pragma unroll
        for (int jj = 0; jj < 8; jj += 4) {
            float4 lv = *(const float4*)(lptr + jj);
            float4 avv = *(const float4*)(aptr + jj);
            float o[4];
            float lvv[4] = {lv.x, lv.y, lv.z, lv.w};
            float agg[4] = {avv.x, avv.y, avv.z, avv.w};
#pragma unroll
            for (int c = 0; c < 4; c++) {
                float x = acc[i][jj + c] + brv[jj + c];
                float g = 1.0f / (1.0f + expf(-x));
                o[c] = g * agg[c] + (1.0f - g) * lvv[c];
            }
            *(float4*)(optr + jj) = make_float4(o[0], o[1], o[2], o[3]);
        }
    }
}

// ---------------------------------------------------------------------------
// Launch
// ---------------------------------------------------------------------------
extern "C" void kernel_launch(void* const* d_in, const int* in_sizes, int n_in,
                              void* d_out, int out_size) {
    const float* right_embed = (const float*)d_in[0];
    const float* W1          = (const float*)d_in[1];
    const float* Wr          = (const float*)d_in[2];
    const float* br          = (const float*)d_in[3];
    const float* edge_vals   = (const float*)d_in[4];
    const int*   edge_rows   = (const int*)d_in[5];
    const int*   edge_cols   = (const int*)d_in[6];
    const int*   perm        = (const int*)d_in[7];

    const int E = in_sizes[4];
    const int N = in_sizes[7];

    float* out = (float*)d_out;

    // 1. CSR row pointers from sorted edge_rows
    {
        int threads = 256;
        int blocks = (N + 1 + threads - 1) / threads;
        build_rowptr<<<blocks, threads>>>(edge_rows, E, N);
    }
    // 2. H = X @ W1
    {
        dim3 grid(DIM / BN, (N + BM - 1) / BM);
        gemm_h<<<grid, 256>>>(right_embed, W1, N);
    }
    // 3. AGG = relu(segment_sum(edge_vals * H[edge_cols]))
    {
        spmm_relu<<<N, 256>>>(edge_vals, edge_cols);
    }
    // 4. gate blend
    {
        dim3 grid(DIM / BN, (N + BM - 1) / BM);
        gemm_gate<<<grid, 256>>>(right_embed, Wr, br, perm, out, N);
    }
}

// round 2
// speedup vs baseline: 1.6070x; 1.6070x over previous
#include <cuda_runtime.h>
#include <cuda_bf16.h>
#include <cuda_fp16.h>
#include <mma.h>
#include <math.h>

using namespace nvcuda;

#define MAXN 100000
#define MAXE 1600000
#define DIM  256

// Scratch (device globals; allocation-free)
__device__ __half2 g_Hh[(size_t)MAXN * (DIM / 2)];   // H = X@W1, fp16
__device__ float   g_AGG[(size_t)MAXN * DIM];        // relu(segment_sum(...))
__device__ int     g_rowptr[MAXN + 1];

// ---------------------------------------------------------------------------
// Kernel 1: row_ptr via binary search over sorted edge_rows
// ---------------------------------------------------------------------------
__global__ void build_rowptr(const int* __restrict__ rows, int E, int Nn) {
    int r = blockIdx.x * blockDim.x + threadIdx.x;
    if (r > Nn) return;
    int lo = 0, hi = E;
    while (lo < hi) {
        int mid = (lo + hi) >> 1;
        if (rows[mid] < r) lo = mid + 1; else hi = mid;
    }
    g_rowptr[r] = lo;
}

// ---------------------------------------------------------------------------
// TF32 tensor-core GEMM tiles: BM=128, BN=64, K chunks of 32.
// 256 threads = 8 warps, warp grid 4(m) x 2(n), each warp 32x32 (2x2 wmma).
// ---------------------------------------------------------------------------
#define BM 128
#define BN 64
#define BKC 32
#define AS_LD 40   // 32 + 8 pad
#define BS_LD 72   // 64 + 8 pad
#define CS_LD 72

// total smem floats needed: max(As 128*40 + Bs 32*72, Cs 128*72)
#define SMEM_FLOATS (128 * 72)

// ---------------------------------------------------------------------------
// Kernel 2: H(half) = X @ W1  (tf32 wmma)
// ---------------------------------------------------------------------------
__global__ __launch_bounds__(256)
void gemm_h(const float* __restrict__ A, const float* __restrict__ B, int M) {
    __shared__ __align__(16) float sm[SMEM_FLOATS];
    float (*As)[AS_LD] = (float(*)[AS_LD])sm;
    float (*Bs)[BS_LD] = (float(*)[BS_LD])(sm + BM * AS_LD);
    float (*Cs)[CS_LD] = (float(*)[CS_LD])sm;

    const int bx = blockIdx.x;          // n block (0..3)
    const int by = blockIdx.y;          // m block
    const int tid = threadIdx.x;
    const int wid = tid >> 5;
    const int wm = wid & 3;             // warp m (0..3) -> 32 rows
    const int wn = wid >> 2;            // warp n (0..1) -> 32 cols
    const int row0 = by * BM;
    const int n0 = bx * BN;

    wmma::fragment<wmma::accumulator, 16, 16, 8, float> cfr[2][2];
#pragma unroll
    for (int i = 0; i < 2; i++)
#pragma unroll
        for (int j = 0; j < 2; j++) wmma::fill_fragment(cfr[i][j], 0.0f);

    for (int k0 = 0; k0 < DIM; k0 += BKC) {
        // load A chunk: 128x32 floats = 1024 float4, 4 per thread
        float4 av[4];
#pragma unroll
        for (int i = 0; i < 4; i++) {
            int lin = (i * 256 + tid) * 4;
            int row = lin >> 5;
            int col = lin & 31;
            int m = min(row0 + row, M - 1);
            av[i] = *(const float4*)(A + (size_t)m * DIM + k0 + col);
        }
        // load B chunk: 32x64 floats = 512 float4, 2 per thread
        float4 bv[2];
#pragma unroll
        for (int i = 0; i < 2; i++) {
            int lin = (i * 256 + tid) * 4;
            int row = lin >> 6;
            int col = lin & 63;
            bv[i] = *(const float4*)(B + (size_t)(k0 + row) * DIM + n0 + col);
        }
        __syncthreads();
#pragma unroll
        for (int i = 0; i < 4; i++) {
            int lin = (i * 256 + tid) * 4;
            *(float4*)&As[lin >> 5][lin & 31] = av[i];
        }
#pragma unroll
        for (int i = 0; i < 2; i++) {
            int lin = (i * 256 + tid) * 4;
            *(float4*)&Bs[lin >> 6][lin & 63] = bv[i];
        }
        __syncthreads();

#pragma unroll
        for (int kk = 0; kk < BKC; kk += 8) {
            wmma::fragment<wmma::matrix_a, 16, 16, 8, wmma::precision::tf32, wmma::row_major> afr[2];
            wmma::fragment<wmma::matrix_b, 16, 16, 8, wmma::precision::tf32, wmma::row_major> bfr[2];
#pragma unroll
            for (int i = 0; i < 2; i++) {
                wmma::load_matrix_sync(afr[i], &As[wm * 32 + i * 16][kk], AS_LD);
#pragma unroll
                for (int t = 0; t < afr[i].num_elements; t++)
                    afr[i].x[t] = wmma::__float_to_tf32(afr[i].x[t]);
            }
#pragma unroll
            for (int j = 0; j < 2; j++) {
                wmma::load_matrix_sync(bfr[j], &Bs[kk][wn * 32 + j * 16], BS_LD);
#pragma unroll
                for (int t = 0; t < bfr[j].num_elements; t++)
                    bfr[j].x[t] = wmma::__float_to_tf32(bfr[j].x[t]);
            }
#pragma unroll
            for (int i = 0; i < 2; i++)
#pragma unroll
                for (int j = 0; j < 2; j++)
                    wmma::mma_sync(cfr[i][j], afr[i], bfr[j], cfr[i][j]);
        }
        __syncthreads();
    }

    // stage C to smem, convert to half2, write
#pragma unroll
    for (int i = 0; i < 2; i++)
#pragma unroll
        for (int j = 0; j < 2; j++)
            wmma::store_matrix_sync(&Cs[wm * 32 + i * 16][wn * 32 + j * 16], cfr[i][j],
                                    CS_LD, wmma::mem_row_major);
    __syncthreads();

    for (int idx = tid; idx < BM * (BN / 2); idx += 256) {
        int row = idx >> 5;           // 32 half2 per row
        int c2 = idx & 31;
        int m = row0 + row;
        if (m >= M) continue;
        float c0 = Cs[row][c2 * 2];
        float c1 = Cs[row][c2 * 2 + 1];
        g_Hh[(size_t)m * (DIM / 2) + bx * (BN / 2) + c2] = __floats2half2_rn(c0, c1);
    }
}

// ---------------------------------------------------------------------------
// Kernel 3: SpMM + ReLU, one block/row, 128 threads (half2 per thread)
// ---------------------------------------------------------------------------
__global__ __launch_bounds__(128)
void spmm_relu(const float* __restrict__ ev, const int* __restrict__ ec) {
    const int r = blockIdx.x;
    const int tid = threadIdx.x;
    const int s = g_rowptr[r];
    const int e = g_rowptr[r + 1];

    __shared__ int   scol[128];
    __shared__ float sval[128];

    float2 a0 = make_float2(0.f, 0.f);
    float2 a1 = make_float2(0.f, 0.f);

    for (int base = s; base < e; base += 128) {
        int cnt = min(128, e - base);
        if (tid < cnt) {
            scol[tid] = ec[base + tid];
            sval[tid] = ev[base + tid];
        }
        __syncthreads();
        int i = 0;
        for (; i + 2 <= cnt; i += 2) {
            float2 h0 = __half22float2(g_Hh[(size_t)scol[i] * 128 + tid]);
            float2 h1 = __half22float2(g_Hh[(size_t)scol[i + 1] * 128 + tid]);
            float v0 = sval[i], v1 = sval[i + 1];
            a0.x = fmaf(v0, h0.x, a0.x);
            a0.y = fmaf(v0, h0.y, a0.y);
            a1.x = fmaf(v1, h1.x, a1.x);
            a1.y = fmaf(v1, h1.y, a1.y);
        }
        if (i < cnt) {
            float2 h0 = __half22float2(g_Hh[(size_t)scol[i] * 128 + tid]);
            float v0 = sval[i];
            a0.x = fmaf(v0, h0.x, a0.x);
            a0.y = fmaf(v0, h0.y, a0.y);
        }
        __syncthreads();
    }
    float2 o = make_float2(fmaxf(a0.x + a1.x, 0.f), fmaxf(a0.y + a1.y, 0.f));
    ((float2*)g_AGG)[(size_t)r * 128 + tid] = o;
}

// ---------------------------------------------------------------------------
// Kernel 4: gate = sigmoid(X[perm] @ Wr + br); out = gate*AGG + (1-gate)*X[perm]
// ---------------------------------------------------------------------------
__global__ __launch_bounds__(256)
void gemm_gate(const float* __restrict__ X, const float* __restrict__ Wr,
               const float* __restrict__ br, const int* __restrict__ perm,
               float* __restrict__ out, int M) {
    __shared__ __align__(16) float sm[SMEM_FLOATS];
    float (*As)[AS_LD] = (float(*)[AS_LD])sm;
    float (*Bs)[BS_LD] = (float(*)[BS_LD])(sm + BM * AS_LD);
    float (*Cs)[CS_LD] = (float(*)[CS_LD])sm;
    __shared__ int pm_s[BM];

    const int bx = blockIdx.x;
    const int by = blockIdx.y;
    const int tid = threadIdx.x;
    const int wid = tid >> 5;
    const int wm = wid & 3;
    const int wn = wid >> 2;
    const int row0 = by * BM;
    const int n0 = bx * BN;

    if (tid < BM) pm_s[tid] = perm[min(row0 + tid, M - 1)];
    __syncthreads();

    wmma::fragment<wmma::accumulator, 16, 16, 8, float> cfr[2][2];
#pragma unroll
    for (int i = 0; i < 2; i++)
#pragma unroll
        for (int j = 0; j < 2; j++) wmma::fill_fragment(cfr[i][j], 0.0f);

    for (int k0 = 0; k0 < DIM; k0 += BKC) {
        float4 av[4];
#pragma unroll
        for (int i = 0; i < 4; i++) {
            int lin = (i * 256 + tid) * 4;
            int row = lin >> 5;
            int col = lin & 31;
            av[i] = *(const float4*)(X + (size_t)pm_s[row] * DIM + k0 + col);
        }
        float4 bv[2];
#pragma unroll
        for (int i = 0; i < 2; i++) {
            int lin = (i * 256 + tid) * 4;
            int row = lin >> 6;
            int col = lin & 63;
            bv[i] = *(const float4*)(Wr + (size_t)(k0 + row) * DIM + n0 + col);
        }
        __syncthreads();
#pragma unroll
        for (int i = 0; i < 4; i++) {
            int lin = (i * 256 + tid) * 4;
            *(float4*)&As[lin >> 5][lin & 31] = av[i];
        }
#pragma unroll
        for (int i = 0; i < 2; i++) {
            int lin = (i * 256 + tid) * 4;
            *(float4*)&Bs[lin >> 6][lin & 63] = bv[i];
        }
        __syncthreads();

#pragma unroll
        for (int kk = 0; kk < BKC; kk += 8) {
            wmma::fragment<wmma::matrix_a, 16, 16, 8, wmma::precision::tf32, wmma::row_major> afr[2];
            wmma::fragment<wmma::matrix_b, 16, 16, 8, wmma::precision::tf32, wmma::row_major> bfr[2];
#pragma unroll
            for (int i = 0; i < 2; i++) {
                wmma::load_matrix_sync(afr[i], &As[wm * 32 + i * 16][kk], AS_LD);
#pragma unroll
                for (int t = 0; t < afr[i].num_elements; t++)
                    afr[i].x[t] = wmma::__float_to_tf32(afr[i].x[t]);
            }
#pragma unroll
            for (int j = 0; j < 2; j++) {
                wmma::load_matrix_sync(bfr[j], &Bs[kk][wn * 32 + j * 16], BS_LD);
#pragma unroll
                for (int t = 0; t < bfr[j].num_elements; t++)
                    bfr[j].x[t] = wmma::__float_to_tf32(bfr[j].x[t]);
            }
#pragma unroll
            for (int i = 0; i < 2; i++)
#pragma unroll
                for (int j = 0; j < 2; j++)
                    wmma::mma_sync(cfr[i][j], afr[i], bfr[j], cfr[i][j]);
        }
        __syncthreads();
    }

#pragma unroll
    for (int i = 0; i < 2; i++)
#pragma unroll
        for (int j = 0; j < 2; j++)
            wmma::store_matrix_sync(&Cs[wm * 32 + i * 16][wn * 32 + j * 16], cfr[i][j],
                                    CS_LD, wmma::mem_row_major);
    __syncthreads();

    // epilogue: sigmoid gate + highway blend (float4 granularity)
    for (int idx = tid; idx < BM * (BN / 4); idx += 256) {
        int row = idx >> 4;           // 16 float4 per row
        int q = idx & 15;
        int m = row0 + row;
        if (m >= M) continue;
        int n = n0 + q * 4;
        float4 cv = *(float4*)&Cs[row][q * 4];
        float4 bvv = *(const float4*)(br + n);
        float4 lv = *(const float4*)(X + (size_t)pm_s[row] * DIM + n);
        float4 avv = *(const float4*)(g_AGG + (size_t)m * DIM + n);
        float c[4] = {cv.x, cv.y, cv.z, cv.w};
        float b[4] = {bvv.x, bvv.y, bvv.z, bvv.w};
        float l[4] = {lv.x, lv.y, lv.z, lv.w};
        float a[4] = {avv.x, avv.y, avv.z, avv.w};
        float o[4];
#pragma unroll
        for (int c4 = 0; c4 < 4; c4++) {
            float x = c[c4] + b[c4];
            float g = 1.0f / (1.0f + expf(-x));
            o[c4] = g * a[c4] + (1.0f - g) * l[c4];
        }
        *(float4*)(out + (size_t)m * DIM + n) = make_float4(o[0], o[1], o[2], o[3]);
    }
}

// ---------------------------------------------------------------------------
// Launch
// ---------------------------------------------------------------------------
extern "C" void kernel_launch(void* const* d_in, const int* in_sizes, int n_in,
                              void* d_out, int out_size) {
    const float* right_embed = (const float*)d_in[0];
    const float* W1          = (const float*)d_in[1];
    const float* Wr          = (const float*)d_in[2];
    const float* br          = (const float*)d_in[3];
    const float* edge_vals   = (const float*)d_in[4];
    const int*   edge_rows   = (const int*)d_in[5];
    const int*   edge_cols   = (const int*)d_in[6];
    const int*   perm        = (const int*)d_in[7];

    const int E = in_sizes[4];
    const int N = in_sizes[7];
    float* out = (float*)d_out;

    {
        int threads = 256;
        int blocks = (N + 1 + threads - 1) / threads;
        build_rowptr<<<blocks, threads>>>(edge_rows, E, N);
    }
    {
        dim3 grid(DIM / BN, (N + BM - 1) / BM);
        gemm_h<<<grid, 256>>>(right_embed, W1, N);
    }
    {
        spmm_relu<<<N, 128>>>(edge_vals, edge_cols);
    }
    {
        dim3 grid(DIM / BN, (N + BM - 1) / BM);
        gemm_gate<<<grid, 256>>>(right_embed, Wr, br, perm, out, N);
    }
}

// round 4
// speedup vs baseline: 1.9896x; 1.2381x over previous
#include <cuda_runtime.h>
#include <cuda_fp16.h>
#include <math.h>

#define MAXN 100000
#define DIM  256

// Scratch (device globals; allocation-free)
__device__ __half2 g_Hh[(size_t)MAXN * (DIM / 2)];    // H = X@W1, fp16
__device__ __half2 g_AGGh[(size_t)MAXN * (DIM / 2)];  // relu(segment_sum), fp16
__device__ int     g_rowptr[MAXN + 1];

// ---------------------------------------------------------------------------
// tf32 helpers
// ---------------------------------------------------------------------------
__device__ __forceinline__ unsigned f2tf(float f) {
    unsigned u;
    asm("cvt.rna.tf32.f32 %0, %1;" : "=r"(u) : "f"(f));
    return u;
}

__device__ __forceinline__ void mma_tf32(float* c, const unsigned* a, const unsigned* b) {
    asm volatile(
        "mma.sync.aligned.m16n8k8.row.col.f32.tf32.tf32.f32 "
        "{%0,%1,%2,%3}, {%4,%5,%6,%7}, {%8,%9}, {%0,%1,%2,%3};\n"
        : "+f"(c[0]), "+f"(c[1]), "+f"(c[2]), "+f"(c[3])
        : "r"(a[0]), "r"(a[1]), "r"(a[2]), "r"(a[3]), "r"(b[0]), "r"(b[1]));
}

// ---------------------------------------------------------------------------
// Kernel 1: row_ptr via binary search over sorted edge_rows
// ---------------------------------------------------------------------------
__global__ void build_rowptr(const int* __restrict__ rows, int E, int Nn) {
    int r = blockIdx.x * blockDim.x + threadIdx.x;
    if (r > Nn) return;
    int lo = 0, hi = E;
    while (lo < hi) {
        int mid = (lo + hi) >> 1;
        if (rows[mid] < r) lo = mid + 1; else hi = mid;
    }
    g_rowptr[r] = lo;
}

// ---------------------------------------------------------------------------
// GEMM config: BM=128, BN=64, BK=16, 8 warps (4m x 2n), warp tile 32x32,
// per-warp mma grid 2(m16) x 4(n8). Double-buffered smem, 1 sync/iter.
// ---------------------------------------------------------------------------
#define BM 128
#define BN 64
#define BK 16
#define A_LD 20   // (20r+c) mod 32 distinct for r<8,c<4  -> conflict-free
#define B_LD 72   // (72k+n) mod 32 = 8k+n distinct for k<4,n<8 -> conflict-free

struct GemmCtx {
    int lane, wm, wn, grp, tig;
    int arow, acol, brow, bcol;
};

__device__ __forceinline__ GemmCtx make_ctx(int t) {
    GemmCtx x;
    x.lane = t & 31;
    int wid = t >> 5;
    x.wm = wid & 3;
    x.wn = wid >> 2;
    x.grp = x.lane >> 2;
    x.tig = x.lane & 3;
    x.arow = t >> 1;            // 0..127
    x.acol = (t & 1) * 8;       // 0 or 8
    x.brow = t >> 4;            // 0..15
    x.bcol = (t & 15) * 4;      // 0..60
    return x;
}

#define GEMM_CORE_COMPUTE(buf)                                                  \
    _Pragma("unroll")                                                           \
    for (int kk = 0; kk < BK; kk += 8) {                                        \
        unsigned a[2][4], b[4][2];                                              \
        _Pragma("unroll")                                                       \
        for (int mi = 0; mi < 2; mi++) {                                        \
            int r = cx.wm * 32 + mi * 16 + cx.grp;                              \
            a[mi][0] = As[buf][r][kk + cx.tig];                                 \
            a[mi][1] = As[buf][r + 8][kk + cx.tig];                             \
            a[mi][2] = As[buf][r][kk + cx.tig + 4];                             \
            a[mi][3] = As[buf][r + 8][kk + cx.tig + 4];                         \
        }                                                                       \
        _Pragma("unroll")                                                       \
        for (int nj = 0; nj < 4; nj++) {                                        \
            int n = cx.wn * 32 + nj * 8 + cx.grp;                               \
            b[nj][0] = Bs[buf][kk + cx.tig][n];                                 \
            b[nj][1] = Bs[buf][kk + cx.tig + 4][n];                             \
        }                                                                       \
        _Pragma("unroll")                                                       \
        for (int mi = 0; mi < 2; mi++)                                          \
            _Pragma("unroll")                                                   \
            for (int nj = 0; nj < 4; nj++)                                      \
                mma_tf32(c[mi][nj], a[mi], b[nj]);                              \
    }

#define GEMM_STORE_SMEM(buf)                                                    \
    _Pragma("unroll")                                                           \
    for (int q = 0; q < 4; q++) {                                               \
        As[buf][cx.arow][cx.acol + q]     = f2tf(av0[q]);                       \
        As[buf][cx.arow][cx.acol + 4 + q] = f2tf(av1[q]);                       \
        Bs[buf][cx.brow][cx.bcol + q]     = f2tf(bv[q]);                        \
    }

// ---------------------------------------------------------------------------
// Kernel 2: H(fp16) = X @ W1
// ---------------------------------------------------------------------------
__global__ __launch_bounds__(256)
void gemm_h(const float* __restrict__ A, const float* __restrict__ B, int M) {
    __shared__ unsigned As[2][BM][A_LD];
    __shared__ unsigned Bs[2][BK][B_LD];

    const int t = threadIdx.x;
    const int bx = blockIdx.x;          // 0..3
    const int by = blockIdx.y;
    const int row0 = by * BM;
    const int n0 = bx * BN;
    GemmCtx cx = make_ctx(t);

    const int am = min(row0 + cx.arow, M - 1);
    const float* Ap = A + (size_t)am * DIM + cx.acol;
    const float* Bp = B + (size_t)cx.brow * DIM + n0 + cx.bcol;

    float c[2][4][4];
#pragma unroll
    for (int mi = 0; mi < 2; mi++)
#pragma unroll
        for (int nj = 0; nj < 4; nj++)
#pragma unroll
            for (int q = 0; q < 4; q++) c[mi][nj][q] = 0.f;

    float av0[4], av1[4], bv[4];
    // prologue load k0=0
    *(float4*)av0 = *(const float4*)(Ap);
    *(float4*)av1 = *(const float4*)(Ap + 4);
    *(float4*)bv  = *(const float4*)(Bp);
    GEMM_STORE_SMEM(0);
    __syncthreads();

    int buf = 0;
#pragma unroll 1
    for (int it = 0; it < DIM / BK; it++) {
        if (it + 1 < DIM / BK) {
            int k0 = (it + 1) * BK;
            *(float4*)av0 = *(const float4*)(Ap + k0);
            *(float4*)av1 = *(const float4*)(Ap + k0 + 4);
            *(float4*)bv  = *(const float4*)(Bp + (size_t)k0 * DIM);
        }
        GEMM_CORE_COMPUTE(buf);
        if (it + 1 < DIM / BK) {
            GEMM_STORE_SMEM(buf ^ 1);
            __syncthreads();
        }
        buf ^= 1;
    }

    // epilogue: write fp16 H straight from C fragments
#pragma unroll
    for (int mi = 0; mi < 2; mi++) {
#pragma unroll
        for (int nj = 0; nj < 4; nj++) {
            int r = row0 + cx.wm * 32 + mi * 16 + cx.grp;
            int col = n0 + cx.wn * 32 + nj * 8 + cx.tig * 2;
            if (r < M)
                g_Hh[(size_t)r * 128 + (col >> 1)] = __floats2half2_rn(c[mi][nj][0], c[mi][nj][1]);
            if (r + 8 < M)
                g_Hh[(size_t)(r + 8) * 128 + (col >> 1)] = __floats2half2_rn(c[mi][nj][2], c[mi][nj][3]);
        }
    }
}

// ---------------------------------------------------------------------------
// Kernel 3: SpMM + ReLU, warp per row, fp16 in/out, unroll-4 edge loop
// ---------------------------------------------------------------------------
__device__ __forceinline__ void spmm_accum(float4 p, float v, float* acc) {
    const __half2* h = (const __half2*)&p;
#pragma unroll
    for (int k = 0; k < 4; k++) {
        float2 f = __half22float2(h[k]);
        acc[2 * k]     = fmaf(v, f.x, acc[2 * k]);
        acc[2 * k + 1] = fmaf(v, f.y, acc[2 * k + 1]);
    }
}

__global__ __launch_bounds__(256)
void spmm_relu(const float* __restrict__ ev, const int* __restrict__ ec, int Nrows) {
    int r = blockIdx.x * 8 + (threadIdx.x >> 5);
    if (r >= Nrows) return;
    const int lane = threadIdx.x & 31;
    const int s = g_rowptr[r];
    const int e = g_rowptr[r + 1];
    const float4* H4 = (const float4*)g_Hh;

    float acc[8];
#pragma unroll
    for (int k = 0; k < 8; k++) acc[k] = 0.f;

    int i = s;
    for (; i + 4 <= e; i += 4) {
        int c0 = __ldg(ec + i), c1 = __ldg(ec + i + 1);
        int c2 = __ldg(ec + i + 2), c3 = __ldg(ec + i + 3);
        float v0 = __ldg(ev + i), v1 = __ldg(ev + i + 1);
        float v2 = __ldg(ev + i + 2), v3 = __ldg(ev + i + 3);
        float4 p0 = H4[(size_t)c0 * 32 + lane];
        float4 p1 = H4[(size_t)c1 * 32 + lane];
        float4 p2 = H4[(size_t)c2 * 32 + lane];
        float4 p3 = H4[(size_t)c3 * 32 + lane];
        spmm_accum(p0, v0, acc);
        spmm_accum(p1, v1, acc);
        spmm_accum(p2, v2, acc);
        spmm_accum(p3, v3, acc);
    }
    for (; i < e; i++) {
        int c0 = __ldg(ec + i);
        float v0 = __ldg(ev + i);
        float4 p0 = H4[(size_t)c0 * 32 + lane];
        spmm_accum(p0, v0, acc);
    }

    __half2 o[4];
#pragma unroll
    for (int k = 0; k < 4; k++)
        o[k] = __floats2half2_rn(fmaxf(acc[2 * k], 0.f), fmaxf(acc[2 * k + 1], 0.f));
    ((float4*)g_AGGh)[(size_t)r * 32 + lane] = *(float4*)o;
}

// ---------------------------------------------------------------------------
// Kernel 4: gate = sigmoid(X[perm] @ Wr + br); out = gate*AGG + (1-gate)*X[perm]
// ---------------------------------------------------------------------------
__global__ __launch_bounds__(256)
void gemm_gate(const float* __restrict__ X, const float* __restrict__ Wr,
               const float* __restrict__ brv, const int* __restrict__ perm,
               float* __restrict__ out, int M) {
    __shared__ unsigned As[2][BM][A_LD];
    __shared__ unsigned Bs[2][BK][B_LD];
    __shared__ int pm_s[BM];

    const int t = threadIdx.x;
    const int bx = blockIdx.x;
    const int by = blockIdx.y;
    const int row0 = by * BM;
    const int n0 = bx * BN;
    GemmCtx cx = make_ctx(t);

    if (t < BM) pm_s[t] = perm[min(row0 + t, M - 1)];
    __syncthreads();

    const float* Ap = X + (size_t)pm_s[cx.arow] * DIM + cx.acol;
    const float* Bp = Wr + (size_t)cx.brow * DIM + n0 + cx.bcol;

    float c[2][4][4];
#pragma unroll
    for (int mi = 0; mi < 2; mi++)
#pragma unroll
        for (int nj = 0; nj < 4; nj++)
#pragma unroll
            for (int q = 0; q < 4; q++) c[mi][nj][q] = 0.f;

    float av0[4], av1[4], bv[4];
    *(float4*)av0 = *(const float4*)(Ap);
    *(float4*)av1 = *(const float4*)(Ap + 4);
    *(float4*)bv  = *(const float4*)(Bp);
    GEMM_STORE_SMEM(0);
    __syncthreads();

    int buf = 0;
#pragma unroll 1
    for (int it = 0; it < DIM / BK; it++) {
        if (it + 1 < DIM / BK) {
            int k0 = (it + 1) * BK;
            *(float4*)av0 = *(const float4*)(Ap + k0);
            *(float4*)av1 = *(const float4*)(Ap + k0 + 4);
            *(float4*)bv  = *(const float4*)(Bp + (size_t)k0 * DIM);
        }
        GEMM_CORE_COMPUTE(buf);
        if (it + 1 < DIM / BK) {
            GEMM_STORE_SMEM(buf ^ 1);
            __syncthreads();
        }
        buf ^= 1;
    }

    // epilogue: sigmoid gate + highway blend, straight from C fragments
#pragma unroll
    for (int mi = 0; mi < 2; mi++) {
#pragma unroll
        for (int nj = 0; nj < 4; nj++) {
            int lr = cx.wm * 32 + mi * 16 + cx.grp;
            int col = n0 + cx.wn * 32 + nj * 8 + cx.tig * 2;
            float b0 = brv[col], b1 = brv[col + 1];
#pragma unroll
            for (int half = 0; half < 2; half++) {
                int m = row0 + lr + half * 8;
                if (m >= M) continue;
                int pr = pm_s[lr + half * 8];
                float2 l = *(const float2*)(X + (size_t)pr * DIM + col);
                float2 a = __half22float2(g_AGGh[(size_t)m * 128 + (col >> 1)]);
                float x0 = c[mi][nj][half * 2 + 0] + b0;
                float x1 = c[mi][nj][half * 2 + 1] + b1;
                float g0 = 1.0f / (1.0f + expf(-x0));
                float g1 = 1.0f / (1.0f + expf(-x1));
                float2 o;
                o.x = g0 * a.x + (1.0f - g0) * l.x;
                o.y = g1 * a.y + (1.0f - g1) * l.y;
                *(float2*)(out + (size_t)m * DIM + col) = o;
            }
        }
    }
}

// ---------------------------------------------------------------------------
// Launch
// ---------------------------------------------------------------------------
extern "C" void kernel_launch(void* const* d_in, const int* in_sizes, int n_in,
                              void* d_out, int out_size) {
    const float* right_embed = (const float*)d_in[0];
    const float* W1          = (const float*)d_in[1];
    const float* Wr          = (const float*)d_in[2];
    const float* br          = (const float*)d_in[3];
    const float* edge_vals   = (const float*)d_in[4];
    const int*   edge_rows   = (const int*)d_in[5];
    const int*   edge_cols   = (const int*)d_in[6];
    const int*   perm        = (const int*)d_in[7];

    const int E = in_sizes[4];
    const int N = in_sizes[7];
    float* out = (float*)d_out;

    {
        int threads = 256;
        int blocks = (N + 1 + threads - 1) / threads;
        build_rowptr<<<blocks, threads>>>(edge_rows, E, N);
    }
    {
        dim3 grid(DIM / BN, (N + BM - 1) / BM);
        gemm_h<<<grid, 256>>>(right_embed, W1, N);
    }
    {
        spmm_relu<<<(N + 7) / 8, 256>>>(edge_vals, edge_cols, N);
    }
    {
        dim3 grid(DIM / BN, (N + BM - 1) / BM);
        gemm_gate<<<grid, 256>>>(right_embed, Wr, br, perm, out, N);
    }
}

// round 5
// speedup vs baseline: 2.8481x; 1.4315x over previous
#include <cuda_runtime.h>
#include <cuda_fp16.h>
#include <math.h>

#define MAXN 100000
#define DIM  256

// Scratch (device globals; allocation-free)
__device__ __half2 g_Hh[(size_t)MAXN * (DIM / 2)];    // H = X@W1, fp16
__device__ __half2 g_AGGh[(size_t)MAXN * (DIM / 2)];  // relu(segment_sum), fp16
__device__ int     g_rowptr[MAXN + 1];

// ---------------------------------------------------------------------------
// mma / ldmatrix helpers
// ---------------------------------------------------------------------------
__device__ __forceinline__ unsigned smem_u32(const void* p) {
    return (unsigned)__cvta_generic_to_shared(p);
}
__device__ __forceinline__ void ldsm4(unsigned* r, unsigned addr) {
    asm volatile("ldmatrix.sync.aligned.m8n8.x4.shared.b16 {%0,%1,%2,%3}, [%4];"
                 : "=r"(r[0]), "=r"(r[1]), "=r"(r[2]), "=r"(r[3]) : "r"(addr));
}
__device__ __forceinline__ void ldsm4t(unsigned* r, unsigned addr) {
    asm volatile("ldmatrix.sync.aligned.m8n8.x4.trans.shared.b16 {%0,%1,%2,%3}, [%4];"
                 : "=r"(r[0]), "=r"(r[1]), "=r"(r[2]), "=r"(r[3]) : "r"(addr));
}
__device__ __forceinline__ void mma_f16(float* c, const unsigned* a, const unsigned* b) {
    asm volatile(
        "mma.sync.aligned.m16n8k16.row.col.f32.f16.f16.f32 "
        "{%0,%1,%2,%3}, {%4,%5,%6,%7}, {%8,%9}, {%0,%1,%2,%3};\n"
        : "+f"(c[0]), "+f"(c[1]), "+f"(c[2]), "+f"(c[3])
        : "r"(a[0]), "r"(a[1]), "r"(a[2]), "r"(a[3]), "r"(b[0]), "r"(b[1]));
}
__device__ __forceinline__ uint2 f4toh4(float4 v) {
    __half2 h0 = __floats2half2_rn(v.x, v.y);
    __half2 h1 = __floats2half2_rn(v.z, v.w);
    uint2 u;
    u.x = *(unsigned*)&h0;
    u.y = *(unsigned*)&h1;
    return u;
}

// ---------------------------------------------------------------------------
// Kernel 1: row_ptr via binary search over sorted edge_rows
// ---------------------------------------------------------------------------
__global__ void build_rowptr(const int* __restrict__ rows, int E, int Nn) {
    int r = blockIdx.x * blockDim.x + threadIdx.x;
    if (r > Nn) return;
    int lo = 0, hi = E;
    while (lo < hi) {
        int mid = (lo + hi) >> 1;
        if (rows[mid] < r) lo = mid + 1; else hi = mid;
    }
    g_rowptr[r] = lo;
}

// ---------------------------------------------------------------------------
// GEMM config: fp16 mma m16n8k16. BM=128, BN=64, BK=32.
// 8 warps (4m x 2n), warp tile 32x32 = 2(m16) x 4(n8). Double buffered.
// Smem: A halves stride 40 (conflict-free ldmatrix), B stride 72.
// ---------------------------------------------------------------------------
#define BM 128
#define BN 64
#define BK 32
#define A_LDH 40
#define B_LDH 72
#define KITERS (DIM / BK)

struct GemmCtx {
    int lane, wm, wn, grp, tig;
    int ar, ac;   // A loader: rows ar + i*32 (i<4), col ac
    int brw, bc;  // B loader: rows brw + i*16 (i<2), col bc
};

__device__ __forceinline__ GemmCtx make_ctx(int t) {
    GemmCtx x;
    x.lane = t & 31;
    int wid = t >> 5;
    x.wm = wid & 3;
    x.wn = wid >> 2;
    x.grp = x.lane >> 2;
    x.tig = x.lane & 3;
    x.ar = t >> 3;            // 0..31
    x.ac = (t & 7) * 4;       // 0..28
    x.brw = t >> 4;           // 0..15
    x.bc = (t & 15) * 4;      // 0..60
    return x;
}

// store staged global fp32 tiles into half smem (converted)
#define GEMM_STORE_SMEM(buf)                                                    \
    _Pragma("unroll")                                                           \
    for (int i = 0; i < 4; i++)                                                 \
        *(uint2*)&As[buf][cx.ar + i * 32][cx.ac] = f4toh4(av[i]);               \
    _Pragma("unroll")                                                           \
    for (int i = 0; i < 2; i++)                                                 \
        *(uint2*)&Bs[buf][cx.brw + i * 16][cx.bc] = f4toh4(bvv[i]);

#define GEMM_CORE_COMPUTE(buf)                                                  \
    _Pragma("unroll")                                                           \
    for (int kk = 0; kk < BK; kk += 16) {                                       \
        unsigned a[2][4], b[2][4];                                              \
        _Pragma("unroll")                                                       \
        for (int mi = 0; mi < 2; mi++) {                                        \
            int m0 = cx.wm * 32 + mi * 16;                                      \
            unsigned ad = smem_u32(                                             \
                &As[buf][m0 + (cx.lane & 7) + ((cx.lane >> 3) & 1) * 8]         \
                       [kk + (cx.lane >> 4) * 8]);                              \
            ldsm4(a[mi], ad);                                                   \
        }                                                                       \
        _Pragma("unroll")                                                       \
        for (int g = 0; g < 2; g++) {                                           \
            int nb = cx.wn * 32 + g * 16;                                       \
            unsigned bd = smem_u32(                                             \
                &Bs[buf][kk + (cx.lane & 7) + ((cx.lane >> 3) & 1) * 8]         \
                       [nb + (cx.lane >> 4) * 8]);                              \
            ldsm4t(b[g], bd);                                                   \
        }                                                                       \
        _Pragma("unroll")                                                       \
        for (int mi = 0; mi < 2; mi++)                                          \
            _Pragma("unroll")                                                   \
            for (int nj = 0; nj < 4; nj++)                                      \
                mma_f16(c[mi][nj], a[mi], &b[nj >> 1][(nj & 1) * 2]);           \
    }

// ---------------------------------------------------------------------------
// Kernel 2: H(fp16) = X @ W1
// ---------------------------------------------------------------------------
__global__ __launch_bounds__(256)
void gemm_h(const float* __restrict__ A, const float* __restrict__ B, int M) {
    __shared__ __align__(16) __half As[2][BM][A_LDH];
    __shared__ __align__(16) __half Bs[2][BK][B_LDH];

    const int t = threadIdx.x;
    const int bx = blockIdx.x;          // 0..3
    const int by = blockIdx.y;
    const int row0 = by * BM;
    const int n0 = bx * BN;
    GemmCtx cx = make_ctx(t);

    const float* Ap[4];
#pragma unroll
    for (int i = 0; i < 4; i++) {
        int m = min(row0 + cx.ar + i * 32, M - 1);
        Ap[i] = A + (size_t)m * DIM + cx.ac;
    }
    const float* Bp0 = B + (size_t)cx.brw * DIM + n0 + cx.bc;

    float c[2][4][4];
#pragma unroll
    for (int mi = 0; mi < 2; mi++)
#pragma unroll
        for (int nj = 0; nj < 4; nj++)
#pragma unroll
            for (int q = 0; q < 4; q++) c[mi][nj][q] = 0.f;

    float4 av[4], bvv[2];
#pragma unroll
    for (int i = 0; i < 4; i++) av[i] = *(const float4*)(Ap[i]);
#pragma unroll
    for (int i = 0; i < 2; i++) bvv[i] = *(const float4*)(Bp0 + (size_t)i * 16 * DIM);
    GEMM_STORE_SMEM(0);
    __syncthreads();

    int buf = 0;
#pragma unroll 1
    for (int it = 0; it < KITERS; it++) {
        if (it + 1 < KITERS) {
            int k0 = (it + 1) * BK;
#pragma unroll
            for (int i = 0; i < 4; i++) av[i] = *(const float4*)(Ap[i] + k0);
#pragma unroll
            for (int i = 0; i < 2; i++)
                bvv[i] = *(const float4*)(Bp0 + (size_t)(k0 + i * 16) * DIM);
        }
        GEMM_CORE_COMPUTE(buf);
        if (it + 1 < KITERS) {
            GEMM_STORE_SMEM(buf ^ 1);
            __syncthreads();
        }
        buf ^= 1;
    }

    // epilogue: write fp16 H straight from C fragments
#pragma unroll
    for (int mi = 0; mi < 2; mi++) {
#pragma unroll
        for (int nj = 0; nj < 4; nj++) {
            int r = row0 + cx.wm * 32 + mi * 16 + cx.grp;
            int col = n0 + cx.wn * 32 + nj * 8 + cx.tig * 2;
            if (r < M)
                g_Hh[(size_t)r * 128 + (col >> 1)] = __floats2half2_rn(c[mi][nj][0], c[mi][nj][1]);
            if (r + 8 < M)
                g_Hh[(size_t)(r + 8) * 128 + (col >> 1)] = __floats2half2_rn(c[mi][nj][2], c[mi][nj][3]);
        }
    }
}

// ---------------------------------------------------------------------------
// Kernel 3: SpMM + ReLU, warp per row, fp16 in/out, unroll-4 edge loop
// ---------------------------------------------------------------------------
__device__ __forceinline__ void spmm_accum(float4 p, float v, float* acc) {
    const __half2* h = (const __half2*)&p;
#pragma unroll
    for (int k = 0; k < 4; k++) {
        float2 f = __half22float2(h[k]);
        acc[2 * k]     = fmaf(v, f.x, acc[2 * k]);
        acc[2 * k + 1] = fmaf(v, f.y, acc[2 * k + 1]);
    }
}

__global__ __launch_bounds__(256)
void spmm_relu(const float* __restrict__ ev, const int* __restrict__ ec, int Nrows) {
    int r = blockIdx.x * 8 + (threadIdx.x >> 5);
    if (r >= Nrows) return;
    const int lane = threadIdx.x & 31;
    const int s = g_rowptr[r];
    const int e = g_rowptr[r + 1];
    const float4* H4 = (const float4*)g_Hh;

    float acc[8];
#pragma unroll
    for (int k = 0; k < 8; k++) acc[k] = 0.f;

    int i = s;
    for (; i + 4 <= e; i += 4) {
        int c0 = __ldg(ec + i), c1 = __ldg(ec + i + 1);
        int c2 = __ldg(ec + i + 2), c3 = __ldg(ec + i + 3);
        float v0 = __ldg(ev + i), v1 = __ldg(ev + i + 1);
        float v2 = __ldg(ev + i + 2), v3 = __ldg(ev + i + 3);
        float4 p0 = H4[(size_t)c0 * 32 + lane];
        float4 p1 = H4[(size_t)c1 * 32 + lane];
        float4 p2 = H4[(size_t)c2 * 32 + lane];
        float4 p3 = H4[(size_t)c3 * 32 + lane];
        spmm_accum(p0, v0, acc);
        spmm_accum(p1, v1, acc);
        spmm_accum(p2, v2, acc);
        spmm_accum(p3, v3, acc);
    }
    for (; i < e; i++) {
        int c0 = __ldg(ec + i);
        float v0 = __ldg(ev + i);
        float4 p0 = H4[(size_t)c0 * 32 + lane];
        spmm_accum(p0, v0, acc);
    }

    __half2 o[4];
#pragma unroll
    for (int k = 0; k < 4; k++)
        o[k] = __floats2half2_rn(fmaxf(acc[2 * k], 0.f), fmaxf(acc[2 * k + 1], 0.f));
    ((float4*)g_AGGh)[(size_t)r * 32 + lane] = *(float4*)o;
}

// ---------------------------------------------------------------------------
// Kernel 4: gate = sigmoid(X[perm] @ Wr + br); out = gate*AGG + (1-gate)*X[perm]
// ---------------------------------------------------------------------------
__global__ __launch_bounds__(256)
void gemm_gate(const float* __restrict__ X, const float* __restrict__ Wr,
               const float* __restrict__ brv, const int* __restrict__ perm,
               float* __restrict__ out, int M) {
    __shared__ __align__(16) __half As[2][BM][A_LDH];
    __shared__ __align__(16) __half Bs[2][BK][B_LDH];
    __shared__ int pm_s[BM];

    const int t = threadIdx.x;
    const int bx = blockIdx.x;
    const int by = blockIdx.y;
    const int row0 = by * BM;
    const int n0 = bx * BN;
    GemmCtx cx = make_ctx(t);

    if (t < BM) pm_s[t] = perm[min(row0 + t, M - 1)];
    __syncthreads();

    const float* Ap[4];
#pragma unroll
    for (int i = 0; i < 4; i++)
        Ap[i] = X + (size_t)pm_s[cx.ar + i * 32] * DIM + cx.ac;
    const float* Bp0 = Wr + (size_t)cx.brw * DIM + n0 + cx.bc;

    float c[2][4][4];
#pragma unroll
    for (int mi = 0; mi < 2; mi++)
#pragma unroll
        for (int nj = 0; nj < 4; nj++)
#pragma unroll
            for (int q = 0; q < 4; q++) c[mi][nj][q] = 0.f;

    float4 av[4], bvv[2];
#pragma unroll
    for (int i = 0; i < 4; i++) av[i] = *(const float4*)(Ap[i]);
#pragma unroll
    for (int i = 0; i < 2; i++) bvv[i] = *(const float4*)(Bp0 + (size_t)i * 16 * DIM);
    GEMM_STORE_SMEM(0);
    __syncthreads();

    int buf = 0;
#pragma unroll 1
    for (int it = 0; it < KITERS; it++) {
        if (it + 1 < KITERS) {
            int k0 = (it + 1) * BK;
#pragma unroll
            for (int i = 0; i < 4; i++) av[i] = *(const float4*)(Ap[i] + k0);
#pragma unroll
            for (int i = 0; i < 2; i++)
                bvv[i] = *(const float4*)(Bp0 + (size_t)(k0 + i * 16) * DIM);
        }
        GEMM_CORE_COMPUTE(buf);
        if (it + 1 < KITERS) {
            GEMM_STORE_SMEM(buf ^ 1);
            __syncthreads();
        }
        buf ^= 1;
    }

    // epilogue: sigmoid gate + highway blend, straight from C fragments
#pragma unroll
    for (int mi = 0; mi < 2; mi++) {
#pragma unroll
        for (int nj = 0; nj < 4; nj++) {
            int lr = cx.wm * 32 + mi * 16 + cx.grp;
            int col = n0 + cx.wn * 32 + nj * 8 + cx.tig * 2;
            float b0 = brv[col], b1 = brv[col + 1];
#pragma unroll
            for (int half = 0; half < 2; half++) {
                int m = row0 + lr + half * 8;
                if (m >= M) continue;
                int pr = pm_s[lr + half * 8];
                float2 l = *(const float2*)(X + (size_t)pr * DIM + col);
                float2 a = __half22float2(g_AGGh[(size_t)m * 128 + (col >> 1)]);
                float x0 = c[mi][nj][half * 2 + 0] + b0;
                float x1 = c[mi][nj][half * 2 + 1] + b1;
                float g0 = 1.0f / (1.0f + expf(-x0));
                float g1 = 1.0f / (1.0f + expf(-x1));
                float2 o;
                o.x = g0 * a.x + (1.0f - g0) * l.x;
                o.y = g1 * a.y + (1.0f - g1) * l.y;
                *(float2*)(out + (size_t)m * DIM + col) = o;
            }
        }
    }
}

// ---------------------------------------------------------------------------
// Launch
// ---------------------------------------------------------------------------
extern "C" void kernel_launch(void* const* d_in, const int* in_sizes, int n_in,
                              void* d_out, int out_size) {
    const float* right_embed = (const float*)d_in[0];
    const float* W1          = (const float*)d_in[1];
    const float* Wr          = (const float*)d_in[2];
    const float* br          = (const float*)d_in[3];
    const float* edge_vals   = (const float*)d_in[4];
    const int*   edge_rows   = (const int*)d_in[5];
    const int*   edge_cols   = (const int*)d_in[6];
    const int*   perm        = (const int*)d_in[7];

    const int E = in_sizes[4];
    const int N = in_sizes[7];
    float* out = (float*)d_out;

    {
        int threads = 256;
        int blocks = (N + 1 + threads - 1) / threads;
        build_rowptr<<<blocks, threads>>>(edge_rows, E, N);
    }
    {
        dim3 grid(DIM / BN, (N + BM - 1) / BM);
        gemm_h<<<grid, 256>>>(right_embed, W1, N);
    }
    {
        spmm_relu<<<(N + 7) / 8, 256>>>(edge_vals, edge_cols, N);
    }
    {
        dim3 grid(DIM / BN, (N + BM - 1) / BM);
        gemm_gate<<<grid, 256>>>(right_embed, Wr, br, perm, out, N);
    }
}

// round 12
// speedup vs baseline: 3.5003x; 1.2290x over previous
#include <cuda_runtime.h>
#include <cuda_fp16.h>
#include <math.h>

#define MAXN 100000
#define DIM  256

// Scratch (device globals; allocation-free)
__device__ __half2 g_Xh[(size_t)MAXN * (DIM / 2)];    // fp16 copy of right_embed
__device__ __half2 g_W1h[DIM * (DIM / 2)];
__device__ __half2 g_Wrh[DIM * (DIM / 2)];
__device__ __half2 g_Hh[(size_t)MAXN * (DIM / 2)];    // H = X@W1, fp16
__device__ __half2 g_AGGh[(size_t)MAXN * (DIM / 2)];  // relu(segment_sum), fp16
__device__ int     g_rowptr[MAXN + 1];

// ---------------------------------------------------------------------------
// helpers
// ---------------------------------------------------------------------------
__device__ __forceinline__ unsigned smem_u32(const void* p) {
    return (unsigned)__cvta_generic_to_shared(p);
}
__device__ __forceinline__ void ldsm4(unsigned* r, unsigned addr) {
    asm volatile("ldmatrix.sync.aligned.m8n8.x4.shared.b16 {%0,%1,%2,%3}, [%4];"
                 : "=r"(r[0]), "=r"(r[1]), "=r"(r[2]), "=r"(r[3]) : "r"(addr));
}
__device__ __forceinline__ void ldsm4t(unsigned* r, unsigned addr) {
    asm volatile("ldmatrix.sync.aligned.m8n8.x4.trans.shared.b16 {%0,%1,%2,%3}, [%4];"
                 : "=r"(r[0]), "=r"(r[1]), "=r"(r[2]), "=r"(r[3]) : "r"(addr));
}
__device__ __forceinline__ void mma_f16(float* c, const unsigned* a, const unsigned* b) {
    asm volatile(
        "mma.sync.aligned.m16n8k16.row.col.f32.f16.f16.f32 "
        "{%0,%1,%2,%3}, {%4,%5,%6,%7}, {%8,%9}, {%0,%1,%2,%3};\n"
        : "+f"(c[0]), "+f"(c[1]), "+f"(c[2]), "+f"(c[3])
        : "r"(a[0]), "r"(a[1]), "r"(a[2]), "r"(a[3]), "r"(b[0]), "r"(b[1]));
}
__device__ __forceinline__ void cp16(void* dst, const void* src) {
    unsigned d = smem_u32(dst);
    asm volatile("cp.async.cg.shared.global [%0], [%1], 16;\n" :: "r"(d), "l"(src));
}
#define CP_COMMIT() asm volatile("cp.async.commit_group;\n" ::: "memory")
#define CP_WAIT(n)  asm volatile("cp.async.wait_group %0;\n" :: "n"(n) : "memory")

// ---------------------------------------------------------------------------
// Kernel 0: fp32 -> fp16 conversion. Destination selected INSIDE device code
// (passing a __device__ symbol from host was the R9-R11 crash).
// which: 0 -> g_Xh, 1 -> g_W1h, 2 -> g_Wrh
// ---------------------------------------------------------------------------
__global__ void convert_fp16(const float* __restrict__ src, int which, int n4) {
    int i = blockIdx.x * blockDim.x + threadIdx.x;
    if (i >= n4) return;
    __half2* dst = (which == 0) ? g_Xh : (which == 1) ? g_W1h : g_Wrh;
    float4 v = *(const float4*)(src + (size_t)i * 4);
    uint2 u;
    __half2 h0 = __floats2half2_rn(v.x, v.y);
    __half2 h1 = __floats2half2_rn(v.z, v.w);
    u.x = *(unsigned*)&h0;
    u.y = *(unsigned*)&h1;
    *(uint2*)(dst + (size_t)i * 2) = u;
}

// ---------------------------------------------------------------------------
// Kernel 1: row_ptr via binary search over sorted edge_rows
// ---------------------------------------------------------------------------
__global__ void build_rowptr(const int* __restrict__ rows, int E, int Nn) {
    int r = blockIdx.x * blockDim.x + threadIdx.x;
    if (r > Nn) return;
    int lo = 0, hi = E;
    while (lo < hi) {
        int mid = (lo + hi) >> 1;
        if (rows[mid] < r) lo = mid + 1; else hi = mid;
    }
    g_rowptr[r] = lo;
}

// ---------------------------------------------------------------------------
// GEMM config: fp16 mma m16n8k16. BM=128, BN=128, BK=32.
// 256 threads = 8 warps (4m x 2n), warp tile 32x64 = 2(m16) x 8(n8).
// 2-stage cp.async double buffer in STATIC smem (37.9KB).
// ---------------------------------------------------------------------------
#define BM 128
#define BN 128
#define BK 32
#define A_LDH 40
#define B_LDH 136
#define KITERS (DIM / BK)   // 8

#define GEMM_ISSUE_STAGE(s, k0)                                                 \
    {                                                                           \
        cp16(&As[s][arow][acol0], Agp + k0);                                    \
        cp16(&As[s][arow][acol0 + 8], Agp + k0 + 8);                            \
        cp16(&Bs[s][brow][bcol], Bgp + (size_t)k0 * DIM);                       \
        cp16(&Bs[s][brow + 16][bcol], Bgp + (size_t)(k0 + 16) * DIM);           \
        CP_COMMIT();                                                            \
    }

#define GEMM_CORE_COMPUTE(s)                                                    \
    _Pragma("unroll")                                                           \
    for (int kk = 0; kk < BK; kk += 16) {                                       \
        unsigned a[2][4], b[4][4];                                              \
        _Pragma("unroll")                                                       \
        for (int mi = 0; mi < 2; mi++) {                                        \
            int m0 = wm * 32 + mi * 16;                                         \
            unsigned ad = smem_u32(                                             \
                &As[s][m0 + (lane & 7) + ((lane >> 3) & 1) * 8]                 \
                     [kk + (lane >> 4) * 8]);                                   \
            ldsm4(a[mi], ad);                                                   \
        }                                                                       \
        _Pragma("unroll")                                                       \
        for (int g = 0; g < 4; g++) {                                           \
            int nb = wn * 64 + g * 16;                                          \
            unsigned bd = smem_u32(                                             \
                &Bs[s][kk + (lane & 7) + ((lane >> 3) & 1) * 8]                 \
                     [nb + (lane >> 4) * 8]);                                   \
            ldsm4t(b[g], bd);                                                   \
        }                                                                       \
        _Pragma("unroll")                                                       \
        for (int mi = 0; mi < 2; mi++)                                          \
            _Pragma("unroll")                                                   \
            for (int nj = 0; nj < 8; nj++)                                      \
                mma_f16(c[mi][nj], a[mi], &b[nj >> 1][(nj & 1) * 2]);           \
    }

// Steady state: 2 groups pending -> wait_group 1. Last iteration: only one
// group pending -> wait_group 0.
#define GEMM_PIPELINE_BODY                                                      \
    GEMM_ISSUE_STAGE(0, 0);                                                     \
    GEMM_ISSUE_STAGE(1, BK);                                                    \
    _Pragma("unroll 1")                                                         \
    for (int it = 0; it < KITERS; it++) {                                       \
        if (it + 1 < KITERS) { CP_WAIT(1); } else { CP_WAIT(0); }               \
        __syncthreads();                                                        \
        GEMM_CORE_COMPUTE(it & 1);                                              \
        __syncthreads();                                                        \
        if (it + 2 < KITERS) GEMM_ISSUE_STAGE(it & 1, (it + 2) * BK);           \
    }

// ---------------------------------------------------------------------------
// Kernel 2: H(fp16) = Xh @ W1h
// ---------------------------------------------------------------------------
__global__ __launch_bounds__(256)
void gemm_h(int M) {
    __shared__ __align__(16) __half As[2][BM][A_LDH];
    __shared__ __align__(16) __half Bs[2][BK][B_LDH];

    const int t = threadIdx.x;
    const int lane = t & 31;
    const int wid = t >> 5;
    const int wm = wid & 3;
    const int wn = wid >> 2;
    const int grp = lane >> 2;
    const int tig = lane & 3;
    const int n0 = blockIdx.x * BN;
    const int row0 = blockIdx.y * BM;

    const int arow = t >> 1;
    const int acol0 = (t & 1) * 16;
    const int brow = t >> 4;
    const int bcol = (t & 15) * 8;

    const __half* Agp = (const __half*)g_Xh + (size_t)min(row0 + arow, M - 1) * DIM + acol0;
    const __half* Bgp = (const __half*)g_W1h + (size_t)brow * DIM + n0 + bcol;

    float c[2][8][4];
#pragma unroll
    for (int mi = 0; mi < 2; mi++)
#pragma unroll
        for (int nj = 0; nj < 8; nj++)
#pragma unroll
            for (int q = 0; q < 4; q++) c[mi][nj][q] = 0.f;

    GEMM_PIPELINE_BODY;

#pragma unroll
    for (int mi = 0; mi < 2; mi++) {
#pragma unroll
        for (int nj = 0; nj < 8; nj++) {
            int r = row0 + wm * 32 + mi * 16 + grp;
            int col = n0 + wn * 64 + nj * 8 + tig * 2;
            if (r < M)
                g_Hh[(size_t)r * 128 + (col >> 1)] = __floats2half2_rn(c[mi][nj][0], c[mi][nj][1]);
            if (r + 8 < M)
                g_Hh[(size_t)(r + 8) * 128 + (col >> 1)] = __floats2half2_rn(c[mi][nj][2], c[mi][nj][3]);
        }
    }
}

// ---------------------------------------------------------------------------
// Kernel 3: SpMM + ReLU, warp per row, fp16 in/out, unroll-4 edge loop
// ---------------------------------------------------------------------------
__device__ __forceinline__ void spmm_accum(float4 p, float v, float* acc) {
    const __half2* h = (const __half2*)&p;
#pragma unroll
    for (int k = 0; k < 4; k++) {
        float2 f = __half22float2(h[k]);
        acc[2 * k]     = fmaf(v, f.x, acc[2 * k]);
        acc[2 * k + 1] = fmaf(v, f.y, acc[2 * k + 1]);
    }
}

__global__ __launch_bounds__(256)
void spmm_relu(const float* __restrict__ ev, const int* __restrict__ ec, int Nrows) {
    int r = blockIdx.x * 8 + (threadIdx.x >> 5);
    if (r >= Nrows) return;
    const int lane = threadIdx.x & 31;
    const int s = g_rowptr[r];
    const int e = g_rowptr[r + 1];
    const float4* H4 = (const float4*)g_Hh;

    float acc[8];
#pragma unroll
    for (int k = 0; k < 8; k++) acc[k] = 0.f;

    int i = s;
    for (; i + 4 <= e; i += 4) {
        int c0 = __ldg(ec + i), c1 = __ldg(ec + i + 1);
        int c2 = __ldg(ec + i + 2), c3 = __ldg(ec + i + 3);
        float v0 = __ldg(ev + i), v1 = __ldg(ev + i + 1);
        float v2 = __ldg(ev + i + 2), v3 = __ldg(ev + i + 3);
        float4 p0 = H4[(size_t)c0 * 32 + lane];
        float4 p1 = H4[(size_t)c1 * 32 + lane];
        float4 p2 = H4[(size_t)c2 * 32 + lane];
        float4 p3 = H4[(size_t)c3 * 32 + lane];
        spmm_accum(p0, v0, acc);
        spmm_accum(p1, v1, acc);
        spmm_accum(p2, v2, acc);
        spmm_accum(p3, v3, acc);
    }
    for (; i < e; i++) {
        int c0 = __ldg(ec + i);
        float v0 = __ldg(ev + i);
        float4 p0 = H4[(size_t)c0 * 32 + lane];
        spmm_accum(p0, v0, acc);
    }

    __half2 o[4];
#pragma unroll
    for (int k = 0; k < 4; k++)
        o[k] = __floats2half2_rn(fmaxf(acc[2 * k], 0.f), fmaxf(acc[2 * k + 1], 0.f));
    ((float4*)g_AGGh)[(size_t)r * 32 + lane] = *(float4*)o;
}

// ---------------------------------------------------------------------------
// Kernel 4: gate = sigmoid(Xh[perm] @ Wrh + br); out = gate*AGG + (1-gate)*Xh[perm]
// ---------------------------------------------------------------------------
__global__ __launch_bounds__(256)
void gemm_gate(const float* __restrict__ brv, const int* __restrict__ perm,
               float* __restrict__ out, int M) {
    __shared__ __align__(16) __half As[2][BM][A_LDH];
    __shared__ __align__(16) __half Bs[2][BK][B_LDH];
    __shared__ int pm_s[BM];

    const int t = threadIdx.x;
    const int lane = t & 31;
    const int wid = t >> 5;
    const int wm = wid & 3;
    const int wn = wid >> 2;
    const int grp = lane >> 2;
    const int tig = lane & 3;
    const int n0 = blockIdx.x * BN;
    const int row0 = blockIdx.y * BM;

    if (t < BM) pm_s[t] = perm[min(row0 + t, M - 1)];
    __syncthreads();

    const int arow = t >> 1;
    const int acol0 = (t & 1) * 16;
    const int brow = t >> 4;
    const int bcol = (t & 15) * 8;

    const __half* Agp = (const __half*)g_Xh + (size_t)pm_s[arow] * DIM + acol0;
    const __half* Bgp = (const __half*)g_Wrh + (size_t)brow * DIM + n0 + bcol;

    float c[2][8][4];
#pragma unroll
    for (int mi = 0; mi < 2; mi++)
#pragma unroll
        for (int nj = 0; nj < 8; nj++)
#pragma unroll
            for (int q = 0; q < 4; q++) c[mi][nj][q] = 0.f;

    GEMM_PIPELINE_BODY;

#pragma unroll
    for (int mi = 0; mi < 2; mi++) {
#pragma unroll
        for (int nj = 0; nj < 8; nj++) {
            int lr = wm * 32 + mi * 16 + grp;
            int col = n0 + wn * 64 + nj * 8 + tig * 2;
            float b0 = brv[col], b1 = brv[col + 1];
#pragma unroll
            for (int half = 0; half < 2; half++) {
                int m = row0 + lr + half * 8;
                if (m >= M) continue;
                int pr = pm_s[lr + half * 8];
                float2 l = __half22float2(g_Xh[(size_t)pr * 128 + (col >> 1)]);
                float2 a = __half22float2(g_AGGh[(size_t)m * 128 + (col >> 1)]);
                float x0 = c[mi][nj][half * 2 + 0] + b0;
                float x1 = c[mi][nj][half * 2 + 1] + b1;
                float g0 = 1.0f / (1.0f + expf(-x0));
                float g1 = 1.0f / (1.0f + expf(-x1));
                float2 o;
                o.x = g0 * a.x + (1.0f - g0) * l.x;
                o.y = g1 * a.y + (1.0f - g1) * l.y;
                *(float2*)(out + (size_t)m * DIM + col) = o;
            }
        }
    }
}

// ---------------------------------------------------------------------------
// Launch (no static state, no attribute calls, no device symbols as args)
// ---------------------------------------------------------------------------
extern "C" void kernel_launch(void* const* d_in, const int* in_sizes, int n_in,
                              void* d_out, int out_size) {
    const float* right_embed = (const float*)d_in[0];
    const float* W1          = (const float*)d_in[1];
    const float* Wr          = (const float*)d_in[2];
    const float* br          = (const float*)d_in[3];
    const float* edge_vals   = (const float*)d_in[4];
    const int*   edge_rows   = (const int*)d_in[5];
    const int*   edge_cols   = (const int*)d_in[6];
    const int*   perm        = (const int*)d_in[7];

    const int E = in_sizes[4];
    const int N = in_sizes[7];
    float* out = (float*)d_out;

    // 0. fp16 conversions (destination selected inside the kernel)
    {
        int n4 = N * (DIM / 4);
        convert_fp16<<<(n4 + 255) / 256, 256>>>(right_embed, 0, n4);
        int w4 = DIM * (DIM / 4);
        convert_fp16<<<(w4 + 255) / 256, 256>>>(W1, 1, w4);
        convert_fp16<<<(w4 + 255) / 256, 256>>>(Wr, 2, w4);
    }
    // 1. CSR row pointers
    {
        int threads = 256;
        int blocks = (N + 1 + threads - 1) / threads;
        build_rowptr<<<blocks, threads>>>(edge_rows, E, N);
    }
    // 2. H = Xh @ W1h
    {
        dim3 grid(DIM / BN, (N + BM - 1) / BM);
        gemm_h<<<grid, 256>>>(N);
    }
    // 3. SpMM + ReLU
    {
        spmm_relu<<<(N + 7) / 8, 256>>>(edge_vals, edge_cols, N);
    }
    // 4. gate blend
    {
        dim3 grid(DIM / BN, (N + BM - 1) / BM);
        gemm_gate<<<grid, 256>>>(br, perm, out, N);
    }
}

// round 13
// speedup vs baseline: 3.5739x; 1.0210x over previous
#include <cuda_runtime.h>
#include <cuda_fp16.h>
#include <math.h>

#define MAXN 100000
#define DIM  256

// Scratch (device globals; allocation-free)
__device__ __half2 g_Xh[(size_t)MAXN * (DIM / 2)];    // fp16 copy of right_embed
__device__ __half2 g_W1h[DIM * (DIM / 2)];
__device__ __half2 g_Wrh[DIM * (DIM / 2)];
__device__ __half2 g_Hh[(size_t)MAXN * (DIM / 2)];    // H = X@W1, fp16
__device__ __half2 g_AGGh[(size_t)MAXN * (DIM / 2)];  // relu(segment_sum), fp16
__device__ int     g_rowptr[MAXN + 1];

// ---------------------------------------------------------------------------
// helpers
// ---------------------------------------------------------------------------
__device__ __forceinline__ unsigned smem_u32(const void* p) {
    return (unsigned)__cvta_generic_to_shared(p);
}
__device__ __forceinline__ void ldsm4(unsigned* r, unsigned addr) {
    asm volatile("ldmatrix.sync.aligned.m8n8.x4.shared.b16 {%0,%1,%2,%3}, [%4];"
                 : "=r"(r[0]), "=r"(r[1]), "=r"(r[2]), "=r"(r[3]) : "r"(addr));
}
__device__ __forceinline__ void ldsm4t(unsigned* r, unsigned addr) {
    asm volatile("ldmatrix.sync.aligned.m8n8.x4.trans.shared.b16 {%0,%1,%2,%3}, [%4];"
                 : "=r"(r[0]), "=r"(r[1]), "=r"(r[2]), "=r"(r[3]) : "r"(addr));
}
__device__ __forceinline__ void mma_f16(float* c, const unsigned* a, const unsigned* b) {
    asm volatile(
        "mma.sync.aligned.m16n8k16.row.col.f32.f16.f16.f32 "
        "{%0,%1,%2,%3}, {%4,%5,%6,%7}, {%8,%9}, {%0,%1,%2,%3};\n"
        : "+f"(c[0]), "+f"(c[1]), "+f"(c[2]), "+f"(c[3])
        : "r"(a[0]), "r"(a[1]), "r"(a[2]), "r"(a[3]), "r"(b[0]), "r"(b[1]));
}
__device__ __forceinline__ void cp16(void* dst, const void* src) {
    unsigned d = smem_u32(dst);
    asm volatile("cp.async.cg.shared.global [%0], [%1], 16;\n" :: "r"(d), "l"(src));
}
#define CP_COMMIT() asm volatile("cp.async.commit_group;\n" ::: "memory")
#define CP_WAIT(n)  asm volatile("cp.async.wait_group %0;\n" :: "n"(n) : "memory")

__device__ __forceinline__ uint2 f4toh4(float4 v) {
    __half2 h0 = __floats2half2_rn(v.x, v.y);
    __half2 h1 = __floats2half2_rn(v.z, v.w);
    uint2 u;
    u.x = *(unsigned*)&h0;
    u.y = *(unsigned*)&h1;
    return u;
}

// ---------------------------------------------------------------------------
// Kernel 0a: X fp32 -> fp16 (dst chosen inside device code)
// ---------------------------------------------------------------------------
__global__ void convert_x(const float* __restrict__ src, int n4) {
    int i = blockIdx.x * blockDim.x + threadIdx.x;
    if (i >= n4) return;
    float4 v = *(const float4*)(src + (size_t)i * 4);
    *(uint2*)(g_Xh + (size_t)i * 2) = f4toh4(v);
}

// Kernel 0b: both weight matrices in one launch
__global__ void convert_w(const float* __restrict__ W1, const float* __restrict__ Wr) {
    const int w4 = DIM * (DIM / 4);                 // 16384 float4 per matrix
    int i = blockIdx.x * blockDim.x + threadIdx.x;  // 0 .. 2*w4-1
    if (i < w4) {
        float4 v = *(const float4*)(W1 + (size_t)i * 4);
        *(uint2*)(g_W1h + (size_t)i * 2) = f4toh4(v);
    } else if (i < 2 * w4) {
        int j = i - w4;
        float4 v = *(const float4*)(Wr + (size_t)j * 4);
        *(uint2*)(g_Wrh + (size_t)j * 2) = f4toh4(v);
    }
}

// ---------------------------------------------------------------------------
// Kernel 1: row_ptr via boundary scatter over sorted edge_rows (one pass,
// coalesced reads; replaces the latency-bound per-row binary search)
// ---------------------------------------------------------------------------
__global__ void build_rowptr_fast(const int* __restrict__ rows, int E, int Nn) {
    int i = blockIdx.x * blockDim.x + threadIdx.x;
    if (i >= E) return;
    int r = rows[i];
    if (i == 0) {
        for (int q = 0; q <= r; q++) g_rowptr[q] = 0;
    } else {
        int rp = rows[i - 1];
        for (int q = rp + 1; q <= r; q++) g_rowptr[q] = i;
    }
    if (i == E - 1) {
        for (int q = r + 1; q <= Nn; q++) g_rowptr[q] = E;
    }
}

// ---------------------------------------------------------------------------
// GEMM config: fp16 mma m16n8k16. BM=128, BN=128, BK=32.
// 256 threads = 8 warps (4m x 2n), warp tile 32x64 = 2(m16) x 8(n8).
// 2-stage cp.async double buffer in STATIC smem (37.9KB).
// ---------------------------------------------------------------------------
#define BM 128
#define BN 128
#define BK 32
#define A_LDH 40
#define B_LDH 136
#define KITERS (DIM / BK)   // 8

#define GEMM_ISSUE_STAGE(s, k0)                                                 \
    {                                                                           \
        cp16(&As[s][arow][acol0], Agp + k0);                                    \
        cp16(&As[s][arow][acol0 + 8], Agp + k0 + 8);                            \
        cp16(&Bs[s][brow][bcol], Bgp + (size_t)k0 * DIM);                       \
        cp16(&Bs[s][brow + 16][bcol], Bgp + (size_t)(k0 + 16) * DIM);           \
        CP_COMMIT();                                                            \
    }

#define GEMM_CORE_COMPUTE(s)                                                    \
    _Pragma("unroll")                                                           \
    for (int kk = 0; kk < BK; kk += 16) {                                       \
        unsigned a[2][4], b[4][4];                                              \
        _Pragma("unroll")                                                       \
        for (int mi = 0; mi < 2; mi++) {                                        \
            int m0 = wm * 32 + mi * 16;                                         \
            unsigned ad = smem_u32(                                             \
                &As[s][m0 + (lane & 7) + ((lane >> 3) & 1) * 8]                 \
                     [kk + (lane >> 4) * 8]);                                   \
            ldsm4(a[mi], ad);                                                   \
        }                                                                       \
        _Pragma("unroll")                                                       \
        for (int g = 0; g < 4; g++) {                                           \
            int nb = wn * 64 + g * 16;                                          \
            unsigned bd = smem_u32(                                             \
                &Bs[s][kk + (lane & 7) + ((lane >> 3) & 1) * 8]                 \
                     [nb + (lane >> 4) * 8]);                                   \
            ldsm4t(b[g], bd);                                                   \
        }                                                                       \
        _Pragma("unroll")                                                       \
        for (int mi = 0; mi < 2; mi++)                                          \
            _Pragma("unroll")                                                   \
            for (int nj = 0; nj < 8; nj++)                                      \
                mma_f16(c[mi][nj], a[mi], &b[nj >> 1][(nj & 1) * 2]);           \
    }

#define GEMM_PIPELINE_BODY                                                      \
    GEMM_ISSUE_STAGE(0, 0);                                                     \
    GEMM_ISSUE_STAGE(1, BK);                                                    \
    _Pragma("unroll 1")                                                         \
    for (int it = 0; it < KITERS; it++) {                                       \
        if (it + 1 < KITERS) { CP_WAIT(1); } else { CP_WAIT(0); }               \
        __syncthreads();                                                        \
        GEMM_CORE_COMPUTE(it & 1);                                              \
        __syncthreads();                                                        \
        if (it + 2 < KITERS) GEMM_ISSUE_STAGE(it & 1, (it + 2) * BK);           \
    }

// ---------------------------------------------------------------------------
// Kernel 2: H(fp16) = Xh @ W1h
// ---------------------------------------------------------------------------
__global__ __launch_bounds__(256)
void gemm_h(int M) {
    __shared__ __align__(16) __half As[2][BM][A_LDH];
    __shared__ __align__(16) __half Bs[2][BK][B_LDH];

    const int t = threadIdx.x;
    const int lane = t & 31;
    const int wid = t >> 5;
    const int wm = wid & 3;
    const int wn = wid >> 2;
    const int grp = lane >> 2;
    const int tig = lane & 3;
    const int n0 = blockIdx.x * BN;
    const int row0 = blockIdx.y * BM;

    const int arow = t >> 1;
    const int acol0 = (t & 1) * 16;
    const int brow = t >> 4;
    const int bcol = (t & 15) * 8;

    const __half* Agp = (const __half*)g_Xh + (size_t)min(row0 + arow, M - 1) * DIM + acol0;
    const __half* Bgp = (const __half*)g_W1h + (size_t)brow * DIM + n0 + bcol;

    float c[2][8][4];
#pragma unroll
    for (int mi = 0; mi < 2; mi++)
#pragma unroll
        for (int nj = 0; nj < 8; nj++)
#pragma unroll
            for (int q = 0; q < 4; q++) c[mi][nj][q] = 0.f;

    GEMM_PIPELINE_BODY;

#pragma unroll
    for (int mi = 0; mi < 2; mi++) {
#pragma unroll
        for (int nj = 0; nj < 8; nj++) {
            int r = row0 + wm * 32 + mi * 16 + grp;
            int col = n0 + wn * 64 + nj * 8 + tig * 2;
            if (r < M)
                g_Hh[(size_t)r * 128 + (col >> 1)] = __floats2half2_rn(c[mi][nj][0], c[mi][nj][1]);
            if (r + 8 < M)
                g_Hh[(size_t)(r + 8) * 128 + (col >> 1)] = __floats2half2_rn(c[mi][nj][2], c[mi][nj][3]);
        }
    }
}

// ---------------------------------------------------------------------------
// Kernel 3: SpMM + ReLU, warp per row, unroll-8 main loop (MLP 8)
// ---------------------------------------------------------------------------
__device__ __forceinline__ void spmm_accum(float4 p, float v, float* acc) {
    const __half2* h = (const __half2*)&p;
#pragma unroll
    for (int k = 0; k < 4; k++) {
        float2 f = __half22float2(h[k]);
        acc[2 * k]     = fmaf(v, f.x, acc[2 * k]);
        acc[2 * k + 1] = fmaf(v, f.y, acc[2 * k + 1]);
    }
}

__global__ __launch_bounds__(256)
void spmm_relu(const float* __restrict__ ev, const int* __restrict__ ec, int Nrows) {
    int r = blockIdx.x * 8 + (threadIdx.x >> 5);
    if (r >= Nrows) return;
    const int lane = threadIdx.x & 31;
    const int s = g_rowptr[r];
    const int e = g_rowptr[r + 1];
    const float4* H4 = (const float4*)g_Hh;

    float acc[8];
#pragma unroll
    for (int k = 0; k < 8; k++) acc[k] = 0.f;

    int i = s;
    for (; i + 8 <= e; i += 8) {
        int   cc[8];
        float vv[8];
        float4 pp[8];
#pragma unroll
        for (int u = 0; u < 8; u++) cc[u] = __ldg(ec + i + u);
#pragma unroll
        for (int u = 0; u < 8; u++) vv[u] = __ldg(ev + i + u);
#pragma unroll
        for (int u = 0; u < 8; u++) pp[u] = H4[(size_t)cc[u] * 32 + lane];
#pragma unroll
        for (int u = 0; u < 8; u++) spmm_accum(pp[u], vv[u], acc);
    }
    if (i + 4 <= e) {
        int   cc[4];
        float vv[4];
        float4 pp[4];
#pragma unroll
        for (int u = 0; u < 4; u++) cc[u] = __ldg(ec + i + u);
#pragma unroll
        for (int u = 0; u < 4; u++) vv[u] = __ldg(ev + i + u);
#pragma unroll
        for (int u = 0; u < 4; u++) pp[u] = H4[(size_t)cc[u] * 32 + lane];
#pragma unroll
        for (int u = 0; u < 4; u++) spmm_accum(pp[u], vv[u], acc);
        i += 4;
    }
    for (; i < e; i++) {
        int c0 = __ldg(ec + i);
        float v0 = __ldg(ev + i);
        float4 p0 = H4[(size_t)c0 * 32 + lane];
        spmm_accum(p0, v0, acc);
    }

    __half2 o[4];
#pragma unroll
    for (int k = 0; k < 4; k++)
        o[k] = __floats2half2_rn(fmaxf(acc[2 * k], 0.f), fmaxf(acc[2 * k + 1], 0.f));
    ((float4*)g_AGGh)[(size_t)r * 32 + lane] = *(float4*)o;
}

// ---------------------------------------------------------------------------
// Kernel 4: gate = sigmoid(Xh[perm] @ Wrh + br); out = gate*AGG + (1-gate)*Xh[perm]
// ---------------------------------------------------------------------------
__global__ __launch_bounds__(256)
void gemm_gate(const float* __restrict__ brv, const int* __restrict__ perm,
               float* __restrict__ out, int M) {
    __shared__ __align__(16) __half As[2][BM][A_LDH];
    __shared__ __align__(16) __half Bs[2][BK][B_LDH];
    __shared__ int pm_s[BM];

    const int t = threadIdx.x;
    const int lane = t & 31;
    const int wid = t >> 5;
    const int wm = wid & 3;
    const int wn = wid >> 2;
    const int grp = lane >> 2;
    const int tig = lane & 3;
    const int n0 = blockIdx.x * BN;
    const int row0 = blockIdx.y * BM;

    if (t < BM) pm_s[t] = perm[min(row0 + t, M - 1)];
    __syncthreads();

    const int arow = t >> 1;
    const int acol0 = (t & 1) * 16;
    const int brow = t >> 4;
    const int bcol = (t & 15) * 8;

    const __half* Agp = (const __half*)g_Xh + (size_t)pm_s[arow] * DIM + acol0;
    const __half* Bgp = (const __half*)g_Wrh + (size_t)brow * DIM + n0 + bcol;

    float c[2][8][4];
#pragma unroll
    for (int mi = 0; mi < 2; mi++)
#pragma unroll
        for (int nj = 0; nj < 8; nj++)
#pragma unroll
            for (int q = 0; q < 4; q++) c[mi][nj][q] = 0.f;

    GEMM_PIPELINE_BODY;

#pragma unroll
    for (int mi = 0; mi < 2; mi++) {
#pragma unroll
        for (int nj = 0; nj < 8; nj++) {
            int lr = wm * 32 + mi * 16 + grp;
            int col = n0 + wn * 64 + nj * 8 + tig * 2;
            float b0 = brv[col], b1 = brv[col + 1];
#pragma unroll
            for (int half = 0; half < 2; half++) {
                int m = row0 + lr + half * 8;
                if (m >= M) continue;
                int pr = pm_s[lr + half * 8];
                float2 l = __half22float2(g_Xh[(size_t)pr * 128 + (col >> 1)]);
                float2 a = __half22float2(g_AGGh[(size_t)m * 128 + (col >> 1)]);
                float x0 = c[mi][nj][half * 2 + 0] + b0;
                float x1 = c[mi][nj][half * 2 + 1] + b1;
                float g0 = 1.0f / (1.0f + expf(-x0));
                float g1 = 1.0f / (1.0f + expf(-x1));
                float2 o;
                o.x = g0 * a.x + (1.0f - g0) * l.x;
                o.y = g1 * a.y + (1.0f - g1) * l.y;
                *(float2*)(out + (size_t)m * DIM + col) = o;
            }
        }
    }
}

// ---------------------------------------------------------------------------
// Launch (no static state, no attribute calls, no device symbols as args)
// ---------------------------------------------------------------------------
extern "C" void kernel_launch(void* const* d_in, const int* in_sizes, int n_in,
                              void* d_out, int out_size) {
    const float* right_embed = (const float*)d_in[0];
    const float* W1          = (const float*)d_in[1];
    const float* Wr          = (const float*)d_in[2];
    const float* br          = (const float*)d_in[3];
    const float* edge_vals   = (const float*)d_in[4];
    const int*   edge_rows   = (const int*)d_in[5];
    const int*   edge_cols   = (const int*)d_in[6];
    const int*   perm        = (const int*)d_in[7];

    const int E = in_sizes[4];
    const int N = in_sizes[7];
    float* out = (float*)d_out;

    // 0. fp16 conversions
    {
        int n4 = N * (DIM / 4);
        convert_x<<<(n4 + 255) / 256, 256>>>(right_embed, n4);
        int w2 = 2 * DIM * (DIM / 4);
        convert_w<<<(w2 + 255) / 256, 256>>>(W1, Wr);
    }
    // 1. CSR row pointers (boundary scatter)
    {
        build_rowptr_fast<<<(E + 255) / 256, 256>>>(edge_rows, E, N);
    }
    // 2. H = Xh @ W1h
    {
        dim3 grid(DIM / BN, (N + BM - 1) / BM);
        gemm_h<<<grid, 256>>>(N);
    }
    // 3. SpMM + ReLU
    {
        spmm_relu<<<(N + 7) / 8, 256>>>(edge_vals, edge_cols, N);
    }
    // 4. gate blend
    {
        dim3 grid(DIM / BN, (N + BM - 1) / BM);
        gemm_gate<<<grid, 256>>>(br, perm, out, N);
    }
}